// round 2
// baseline (speedup 1.0000x reference)
#include <cuda_runtime.h>

// ============================================================================
// OHEM loss (CRAFT hard negative mining), single-data-pass histogram select.
// R2: warp-aggregated smem atomics (match_any + redux.sync), zero-kernel
//     removed (finalize re-zeroes device state after consuming it).
// ============================================================================

#define NBINS   8192
#define BSHIFT  19                  // 32 - 13 bits
#define FPSCALE 262144.0f           // 2^18 fixed-point scale for bin sums
#define INV_FPSCALE (1.0 / 262144.0)
#define SUMMASK ((1ULL << 40) - 1ULL)
#define CNTONE  (1ULL << 40)
#define INVALID_BIN 0x7FFFFFFFu

__device__ unsigned long long g_hist[2 * NBINS];   // zero-init at load; finalize re-zeroes
__device__ unsigned long long g_pos_cnt[2];
__device__ double             g_pos_sum[2];

// Warp-aggregated packed (count|sum) atomic into shared histogram.
// All 32 lanes must be converged (warp-uniform loop trip count guarantees it).
__device__ __forceinline__ void agg_atomic(unsigned long long* __restrict__ sh,
                                           unsigned bin, unsigned fp, int lane)
{
    unsigned grp = __match_any_sync(0xffffffffu, bin);
    if (bin != INVALID_BIN) {
        unsigned cnt = __popc(grp);
        unsigned s   = __reduce_add_sync(grp, fp);
        if (lane == (__ffs(grp) - 1))
            atomicAdd(&sh[bin], (unsigned long long)cnt * CNTONE + (unsigned long long)s);
    }
}

// ---------------------------------------------------------------------------
// Pass 1: fused read of output (float4 = 2 pixels x 2 channels) + both maps.
// Shared-memory privatized histograms: 2 channels x 8192 bins x 8B = 128 KB.
// ---------------------------------------------------------------------------
__global__ __launch_bounds__(1024, 1)
void ohem_pass1(const float4* __restrict__ out4,
                const float2* __restrict__ cm2,
                const float2* __restrict__ am2,
                int npairs)
{
    extern __shared__ unsigned long long sh[];   // [2 * NBINS]
    for (int i = threadIdx.x; i < 2 * NBINS; i += 1024) sh[i] = 0ULL;
    __syncthreads();

    float    psum0 = 0.f, psum1 = 0.f;
    unsigned pcnt0 = 0,   pcnt1 = 0;
    const int lane   = threadIdx.x & 31;
    const int stride = gridDim.x * 1024;

    // npairs % 32 == 0 and lanes are contiguous in p -> trip count is
    // warp-uniform, so full-mask sync intrinsics below are safe.
    for (int p = blockIdx.x * 1024 + threadIdx.x; p < npairs; p += stride) {
        float4 o  = __ldg(out4 + p);
        float2 cm = __ldg(cm2 + p);
        float2 am = __ldg(am2 + p);

        unsigned bin, fp;

        // pixel 0, channel 0
        {
            float d = o.x - cm.x; float l = d * d;
            bin = INVALID_BIN; fp = 0u;
            if (cm.x >= 0.1f)      { pcnt0++; psum0 += l; }
            else if (cm.x <= 0.0f) { bin = __float_as_uint(l) >> BSHIFT;
                                     fp  = __float2uint_rn(l * FPSCALE); }
            agg_atomic(sh, bin, fp, lane);
        }
        // pixel 0, channel 1
        {
            float d = o.y - am.x; float l = d * d;
            bin = INVALID_BIN; fp = 0u;
            if (am.x >= 0.1f)      { pcnt1++; psum1 += l; }
            else if (am.x <= 0.0f) { bin = NBINS + (__float_as_uint(l) >> BSHIFT);
                                     fp  = __float2uint_rn(l * FPSCALE); }
            agg_atomic(sh, bin, fp, lane);
        }
        // pixel 1, channel 0
        {
            float d = o.z - cm.y; float l = d * d;
            bin = INVALID_BIN; fp = 0u;
            if (cm.y >= 0.1f)      { pcnt0++; psum0 += l; }
            else if (cm.y <= 0.0f) { bin = __float_as_uint(l) >> BSHIFT;
                                     fp  = __float2uint_rn(l * FPSCALE); }
            agg_atomic(sh, bin, fp, lane);
        }
        // pixel 1, channel 1
        {
            float d = o.w - am.y; float l = d * d;
            bin = INVALID_BIN; fp = 0u;
            if (am.y >= 0.1f)      { pcnt1++; psum1 += l; }
            else if (am.y <= 0.0f) { bin = NBINS + (__float_as_uint(l) >> BSHIFT);
                                     fp  = __float2uint_rn(l * FPSCALE); }
            agg_atomic(sh, bin, fp, lane);
        }
    }
    __syncthreads();

    // Flush shared histograms to global (spread-address atomics).
    for (int i = threadIdx.x; i < 2 * NBINS; i += 1024) {
        unsigned long long v = sh[i];
        if (v) atomicAdd(&g_hist[i], v);
    }

    // Block-reduce positive stats.
    const unsigned mask = 0xffffffffu;
    for (int off = 16; off; off >>= 1) {
        psum0 += __shfl_down_sync(mask, psum0, off);
        psum1 += __shfl_down_sync(mask, psum1, off);
        pcnt0 += __shfl_down_sync(mask, pcnt0, off);
        pcnt1 += __shfl_down_sync(mask, pcnt1, off);
    }
    __shared__ float    rs0[32], rs1[32];
    __shared__ unsigned rc0[32], rc1[32];
    int w = threadIdx.x >> 5;
    if (lane == 0) { rs0[w] = psum0; rs1[w] = psum1; rc0[w] = pcnt0; rc1[w] = pcnt1; }
    __syncthreads();
    if (w == 0) {
        float    a0 = rs0[lane], a1 = rs1[lane];
        unsigned c0 = rc0[lane], c1 = rc1[lane];
        for (int off = 16; off; off >>= 1) {
            a0 += __shfl_down_sync(mask, a0, off);
            a1 += __shfl_down_sync(mask, a1, off);
            c0 += __shfl_down_sync(mask, c0, off);
            c1 += __shfl_down_sync(mask, c1, off);
        }
        if (lane == 0) {
            atomicAdd(&g_pos_sum[0], (double)a0);
            atomicAdd(&g_pos_sum[1], (double)a1);
            atomicAdd(&g_pos_cnt[0], (unsigned long long)c0);
            atomicAdd(&g_pos_cnt[1], (unsigned long long)c1);
        }
    }
}

// ---------------------------------------------------------------------------
// Finalize: single block suffix-scans each channel's 8192-bin histogram,
// finds the k-th-largest threshold bin, assembles neg_sum, writes the scalar.
// Re-zeroes all device state after consuming it (replaces the zero kernel).
// ---------------------------------------------------------------------------
__global__ __launch_bounds__(1024, 1)
void ohem_finalize(float* __restrict__ out)
{
    __shared__ unsigned  sc[1024];
    __shared__ double    ss[1024];
    __shared__ double    s_negsum[2];
    __shared__ long long s_k[2];
    __shared__ double    sp_sum[2];
    __shared__ long long sp_cnt[2];

    const int t = threadIdx.x;

    if (t < 2) {
        sp_sum[t] = g_pos_sum[t];
        sp_cnt[t] = (long long)g_pos_cnt[t];
        g_pos_sum[t] = 0.0;          // reset for next invocation
        g_pos_cnt[t] = 0ULL;
    }
    __syncthreads();

    for (int c = 0; c < 2; c++) {
        // Load my 8 bins, decode packed count/sum, then zero them.
        unsigned cnt[8];
        double   sum[8];
        unsigned tc = 0; double ts = 0.0;
        #pragma unroll
        for (int j = 0; j < 8; j++) {
            int idx = c * NBINS + t * 8 + j;
            unsigned long long v = g_hist[idx];
            g_hist[idx] = 0ULL;       // reset for next invocation
            cnt[j] = (unsigned)(v >> 40);
            sum[j] = (double)(v & SUMMASK) * INV_FPSCALE;
            tc += cnt[j]; ts += sum[j];
        }
        sc[t] = tc; ss[t] = ts;
        __syncthreads();

        // Inclusive suffix scan over 1024 per-thread totals (Hillis-Steele).
        for (int off = 1; off < 1024; off <<= 1) {
            unsigned a  = sc[t];
            double   b  = ss[t];
            unsigned a2 = (t + off < 1024) ? sc[t + off] : 0u;
            double   b2 = (t + off < 1024) ? ss[t + off] : 0.0;
            __syncthreads();
            sc[t] = a + a2; ss[t] = b + b2;
            __syncthreads();
        }

        long long num_neg = (long long)sc[0];
        long long num_pos = sp_cnt[c];
        long long k = 3 * num_pos;
        if (k < 1000)    k = 1000;
        if (k > num_neg) k = num_neg;

        unsigned SN  = (t < 1023) ? sc[t + 1] : 0u;
        double   SNs = (t < 1023) ? ss[t + 1] : 0.0;
        if (t == 0) { s_negsum[c] = 0.0; s_k[c] = k; }
        __syncthreads();

        if (k > 0) {
            long long cum  = (long long)SN;
            double    cumS = SNs;
            #pragma unroll
            for (int j = 7; j >= 0; j--) {
                long long c2 = cum + (long long)cnt[j];
                if (cum < k && k <= c2) {
                    long long r    = k - cum;
                    double    mean = (cnt[j] > 0) ? (sum[j] / (double)cnt[j]) : 0.0;
                    s_negsum[c] = cumS + (double)r * mean;
                }
                cum  = c2;
                cumS += sum[j];
            }
        }
        __syncthreads();
    }

    if (t == 0) {
        double l0 = (sp_sum[0] + s_negsum[0]) / (double)(sp_cnt[0] + (unsigned long long)s_k[0]);
        double l1 = (sp_sum[1] + s_negsum[1]) / (double)(sp_cnt[1] + (unsigned long long)s_k[1]);
        out[0] = (float)(2.0 * l0 + l1);
    }
}

// ---------------------------------------------------------------------------
extern "C" void kernel_launch(void* const* d_in, const int* in_sizes, int n_in,
                              void* d_out, int out_size)
{
    const float* output = (const float*)d_in[0];   // [B,H,W,2]
    const float* cm     = (const float*)d_in[1];   // [B,H,W]
    const float* am     = (const float*)d_in[2];   // [B,H,W]
    const int n      = in_sizes[1];                // B*H*W
    const int npairs = n / 2;

    cudaFuncSetAttribute(ohem_pass1,
                         cudaFuncAttributeMaxDynamicSharedMemorySize,
                         2 * NBINS * (int)sizeof(unsigned long long));

    ohem_pass1<<<148, 1024, 2 * NBINS * sizeof(unsigned long long)>>>(
        (const float4*)output, (const float2*)cm, (const float2*)am, npairs);
    ohem_finalize<<<1, 1024>>>((float*)d_out);
}

// round 3
// speedup vs baseline: 3.6218x; 3.6218x over previous
#include <cuda_runtime.h>

// ============================================================================
// OHEM loss (CRAFT hard negative mining), single-kernel histogram select.
// R3: plain 64-bit packed smem atomics (aggregation reverted), 4096 bins x
//     2 replicas (halved hot-bin contention), finalize fused into pass1 via
//     last-block pattern (no second kernel, no zero kernel).
// ============================================================================

#define NBINS   4096
#define BSHIFT  20                  // 32 - 12 bits (sign+8exp+3mant)
#define FPSCALE 262144.0f           // 2^18 fixed-point scale for bin sums
#define INV_FPSCALE (1.0 / 262144.0)
#define SUMMASK ((1ULL << 40) - 1ULL)
#define CNTONE  (1ULL << 40)
#define GRID    148

__device__ unsigned long long g_hist[2 * NBINS];   // zero at load; last block re-zeroes
__device__ unsigned long long g_pos_cnt[2];
__device__ double             g_pos_sum[2];
__device__ unsigned           g_done;

__global__ __launch_bounds__(1024, 1)
void ohem_fused(const float4* __restrict__ out4,
                const float2* __restrict__ cm2,
                const float2* __restrict__ am2,
                int npairs,
                float* __restrict__ out)
{
    extern __shared__ unsigned long long sh[];   // [2 replicas][2*NBINS] = 128KB
    for (int i = threadIdx.x; i < 4 * NBINS; i += 1024) sh[i] = 0ULL;
    __syncthreads();

    const int lane = threadIdx.x & 31;
    const int wid  = threadIdx.x >> 5;
    // replica by warp parity: halves same-address conflict degree
    unsigned long long* hist = sh + (wid & 1) * (2 * NBINS);

    float    psum0 = 0.f, psum1 = 0.f;
    unsigned pcnt0 = 0,   pcnt1 = 0;

    const int stride = GRID * 1024;
    for (int p = blockIdx.x * 1024 + threadIdx.x; p < npairs; p += stride) {
        float4 o  = __ldg(out4 + p);
        float2 cm = __ldg(cm2 + p);
        float2 am = __ldg(am2 + p);

        { // pixel 0, channel 0
            float d = o.x - cm.x; float l = d * d;
            if (cm.x >= 0.1f)      { pcnt0++; psum0 += l; }
            else if (cm.x <= 0.0f) {
                unsigned b = __float_as_uint(l) >> BSHIFT;
                atomicAdd(&hist[b], CNTONE | (unsigned long long)__float2uint_rn(l * FPSCALE));
            }
        }
        { // pixel 0, channel 1
            float d = o.y - am.x; float l = d * d;
            if (am.x >= 0.1f)      { pcnt1++; psum1 += l; }
            else if (am.x <= 0.0f) {
                unsigned b = __float_as_uint(l) >> BSHIFT;
                atomicAdd(&hist[NBINS + b], CNTONE | (unsigned long long)__float2uint_rn(l * FPSCALE));
            }
        }
        { // pixel 1, channel 0
            float d = o.z - cm.y; float l = d * d;
            if (cm.y >= 0.1f)      { pcnt0++; psum0 += l; }
            else if (cm.y <= 0.0f) {
                unsigned b = __float_as_uint(l) >> BSHIFT;
                atomicAdd(&hist[b], CNTONE | (unsigned long long)__float2uint_rn(l * FPSCALE));
            }
        }
        { // pixel 1, channel 1
            float d = o.w - am.y; float l = d * d;
            if (am.y >= 0.1f)      { pcnt1++; psum1 += l; }
            else if (am.y <= 0.0f) {
                unsigned b = __float_as_uint(l) >> BSHIFT;
                atomicAdd(&hist[NBINS + b], CNTONE | (unsigned long long)__float2uint_rn(l * FPSCALE));
            }
        }
    }
    __syncthreads();

    // Flush merged replicas to global histogram.
    for (int i = threadIdx.x; i < 2 * NBINS; i += 1024) {
        unsigned long long v = sh[i] + sh[2 * NBINS + i];
        if (v) atomicAdd(&g_hist[i], v);
    }

    // Block-reduce positive stats -> global atomics.
    const unsigned full = 0xffffffffu;
    for (int off = 16; off; off >>= 1) {
        psum0 += __shfl_down_sync(full, psum0, off);
        psum1 += __shfl_down_sync(full, psum1, off);
        pcnt0 += __shfl_down_sync(full, pcnt0, off);
        pcnt1 += __shfl_down_sync(full, pcnt1, off);
    }
    __shared__ float    rs0[32], rs1[32];
    __shared__ unsigned rc0[32], rc1[32];
    if (lane == 0) { rs0[wid] = psum0; rs1[wid] = psum1; rc0[wid] = pcnt0; rc1[wid] = pcnt1; }
    __syncthreads();
    if (wid == 0) {
        float    a0 = rs0[lane], a1 = rs1[lane];
        unsigned c0 = rc0[lane], c1 = rc1[lane];
        for (int off = 16; off; off >>= 1) {
            a0 += __shfl_down_sync(full, a0, off);
            a1 += __shfl_down_sync(full, a1, off);
            c0 += __shfl_down_sync(full, c0, off);
            c1 += __shfl_down_sync(full, c1, off);
        }
        if (lane == 0) {
            atomicAdd(&g_pos_sum[0], (double)a0);
            atomicAdd(&g_pos_sum[1], (double)a1);
            atomicAdd(&g_pos_cnt[0], (unsigned long long)c0);
            atomicAdd(&g_pos_cnt[1], (unsigned long long)c1);
        }
    }

    // ---------------- last-block finalize ----------------
    __shared__ unsigned s_islast;
    __threadfence();
    if (threadIdx.x == 0)
        s_islast = (atomicAdd(&g_done, 1u) == GRID - 1) ? 1u : 0u;
    __syncthreads();
    if (!s_islast) return;

    // Layout: warps 0-15 -> channel 0, warps 16-31 -> channel 1.
    // Each channel: 512 threads x 8 bins.
    const int c    = threadIdx.x >> 9;          // 0 or 1
    const int tloc = threadIdx.x & 511;          // thread within channel
    const int wloc = tloc >> 5;                  // warp within channel (0..15)

    __shared__ double    sp_sum[2];
    __shared__ long long sp_cnt[2];
    if (threadIdx.x < 2) {
        sp_sum[threadIdx.x] = g_pos_sum[threadIdx.x];
        sp_cnt[threadIdx.x] = (long long)g_pos_cnt[threadIdx.x];
        g_pos_sum[threadIdx.x] = 0.0;            // reset for next replay
        g_pos_cnt[threadIdx.x] = 0ULL;
    }
    if (threadIdx.x == 2) g_done = 0u;

    unsigned cnt[8];
    double   sum[8];
    unsigned tc = 0; double ts = 0.0;
    #pragma unroll
    for (int j = 0; j < 8; j++) {
        int idx = c * NBINS + tloc * 8 + j;
        unsigned long long v = g_hist[idx];
        g_hist[idx] = 0ULL;                      // reset for next replay
        cnt[j] = (unsigned)(v >> 40);
        sum[j] = (double)(v & SUMMASK) * INV_FPSCALE;
        tc += cnt[j]; ts += sum[j];
    }

    // Warp inclusive suffix scan (lane holds sum of lanes [lane..31]).
    unsigned ci = tc; double si = ts;
    #pragma unroll
    for (int off = 1; off < 32; off <<= 1) {
        unsigned cc = __shfl_down_sync(full, ci, off);
        double   ssv = __shfl_down_sync(full, si, off);
        if (lane + off < 32) { ci += cc; si += ssv; }
    }

    __shared__ unsigned  wcnt[2][16];
    __shared__ double    wsum[2][16];
    __shared__ unsigned  wabove_c[2][16];
    __shared__ double    wabove_s[2][16];
    __shared__ unsigned  chtot[2];
    if (lane == 0) { wcnt[c][wloc] = ci; wsum[c][wloc] = si; }
    __syncthreads();

    if (threadIdx.x < 32) {                      // 32 lanes cover 2ch x 16 warps
        int cc2 = threadIdx.x >> 4, ww = threadIdx.x & 15;
        unsigned ac = 0; double as = 0.0;
        for (int w2 = ww + 1; w2 < 16; w2++) { ac += wcnt[cc2][w2]; as += wsum[cc2][w2]; }
        wabove_c[cc2][ww] = ac;
        wabove_s[cc2][ww] = as;
        if (ww == 0) chtot[cc2] = ac + wcnt[cc2][0];
    }
    __syncthreads();

    long long num_neg = (long long)chtot[c];
    long long num_pos = sp_cnt[c];
    long long k = 3 * num_pos;
    if (k < 1000)    k = 1000;
    if (k > num_neg) k = num_neg;

    // Suffix (count,sum) strictly above this thread's bin range.
    long long SN  = (long long)(wabove_c[c][wloc] + (ci - tc));
    double    SNs = wabove_s[c][wloc] + (si - ts);

    __shared__ double    s_negsum[2];
    __shared__ long long s_k[2];
    if (tloc == 0) { s_negsum[c] = 0.0; s_k[c] = k; }
    __syncthreads();

    if (k > 0) {
        long long cum  = SN;
        double    cumS = SNs;
        #pragma unroll
        for (int j = 7; j >= 0; j--) {
            long long c2 = cum + (long long)cnt[j];
            if (cum < k && k <= c2) {
                long long r    = k - cum;
                double    mean = (cnt[j] > 0) ? (sum[j] / (double)cnt[j]) : 0.0;
                s_negsum[c] = cumS + (double)r * mean;
            }
            cum  = c2;
            cumS += sum[j];
        }
    }
    __syncthreads();

    if (threadIdx.x == 0) {
        double l0 = (sp_sum[0] + s_negsum[0]) / (double)(sp_cnt[0] + (unsigned long long)s_k[0]);
        double l1 = (sp_sum[1] + s_negsum[1]) / (double)(sp_cnt[1] + (unsigned long long)s_k[1]);
        out[0] = (float)(2.0 * l0 + l1);
    }
}

// ---------------------------------------------------------------------------
extern "C" void kernel_launch(void* const* d_in, const int* in_sizes, int n_in,
                              void* d_out, int out_size)
{
    const float* output = (const float*)d_in[0];   // [B,H,W,2]
    const float* cm     = (const float*)d_in[1];   // [B,H,W]
    const float* am     = (const float*)d_in[2];   // [B,H,W]
    const int n      = in_sizes[1];                // B*H*W
    const int npairs = n / 2;

    cudaFuncSetAttribute(ohem_fused,
                         cudaFuncAttributeMaxDynamicSharedMemorySize,
                         4 * NBINS * (int)sizeof(unsigned long long));

    ohem_fused<<<GRID, 1024, 4 * NBINS * sizeof(unsigned long long)>>>(
        (const float4*)output, (const float2*)cm, (const float2*)am,
        npairs, (float*)d_out);
}